// round 1
// baseline (speedup 1.0000x reference)
#include <cuda_runtime.h>
#include <cstdint>

// Problem constants (fixed shapes from setup_inputs)
#define BB 4
#define NN 8192
#define DD 1024
#define TT 1024
#define INV_TEMP (1.0f / 0.7f)
#define NEG_BIG (-3.402823466e38f)

// Scratch (device globals: no allocation allowed)
__device__ float g_sdiv[BB * NN];   // scores / 0.7
__device__ float g_r[BB * TT];      // row offsets r_i
__device__ float g_v[BB * NN];      // v_j = s_j/0.7 + c_j

// ---- online logsumexp helpers ----
__device__ __forceinline__ void lse_add(float v, float& m, float& s) {
    if (v > m) { s = s * __expf(m - v) + 1.0f; m = v; }
    else       { s += __expf(v - m); }
}
__device__ __forceinline__ void lse_merge(float m2, float s2, float& m, float& s) {
    if (m2 > m) { s = s * __expf(m - m2) + s2; m = m2; }
    else        { s += s2 * __expf(m2 - m); }
}

// ---- kernel 1: scores matvec (b,n,d)x(d) -> sdiv; also zero r ----
__global__ void k_scores(const float* __restrict__ x, const float* __restrict__ rt) {
    int gid = blockIdx.x * blockDim.x + threadIdx.x;
    if (gid < BB * TT) g_r[gid] = 0.0f;
    int gw = gid >> 5;           // one warp per (b, j) row
    int lane = threadIdx.x & 31;
    if (gw >= BB * NN) return;
    const float4* xv = (const float4*)(x + (size_t)gw * DD);
    const float4* rv = (const float4*)rt;
    float acc = 0.0f;
#pragma unroll
    for (int k = 0; k < 8; k++) {
        float4 a = xv[lane + 32 * k];
        float4 b = __ldg(&rv[lane + 32 * k]);
        acc += a.x * b.x + a.y * b.y + a.z * b.z + a.w * b.w;
    }
#pragma unroll
    for (int o = 16; o; o >>= 1) acc += __shfl_down_sync(0xffffffffu, acc, o);
    if (lane == 0) g_sdiv[gw] = acc * INV_TEMP;
}

// ---- col pass: v_j = sdiv_j - lse_i(sdiv_j + g[i,j] + r_i) ----
// block: 256 threads = 64 columns x 4 row-chunks of 256
__global__ void k_col(const float* __restrict__ g) {
    __shared__ float sr[TT];
    __shared__ float pm[4][64];
    __shared__ float ps[4][64];
    int b    = blockIdx.x >> 7;          // 128 column tiles per batch
    int tile = blockIdx.x & 127;
    int jl    = threadIdx.x & 63;
    int chunk = threadIdx.x >> 6;
    int j = tile * 64 + jl;
    for (int i = threadIdx.x; i < TT; i += 256) sr[i] = g_r[b * TT + i];
    __syncthreads();
    float sd = g_sdiv[b * NN + j];
    const float* gp = g + ((size_t)(b * TT + chunk * 256)) * NN + j;
    float m = NEG_BIG, s = 0.0f;
#pragma unroll 4
    for (int i = 0; i < 256; i++) {
        float v = sd + gp[(size_t)i * NN] + sr[chunk * 256 + i];
        lse_add(v, m, s);
    }
    pm[chunk][jl] = m; ps[chunk][jl] = s;
    __syncthreads();
    if (chunk == 0) {
#pragma unroll
        for (int c = 1; c < 4; c++) lse_merge(pm[c][jl], ps[c][jl], m, s);
        float lse = m + logf(s);
        g_v[b * NN + j] = sd - lse;
    }
}

// ---- row pass: r_i = -lse_j(g[i,j] + v_j) ----
// one block (256 threads) per (b, i) row of 8192
__global__ void k_row(const float* __restrict__ g) {
    int b = blockIdx.x >> 10;
    int i = blockIdx.x & 1023;
    const float4* gp = (const float4*)(g + ((size_t)(b * TT + i)) * NN);
    const float4* vp = (const float4*)(g_v + b * NN);
    float m = NEG_BIG, s = 0.0f;
#pragma unroll
    for (int k = 0; k < 8; k++) {
        int idx = threadIdx.x + k * 256;
        float4 a = gp[idx];
        float4 v = vp[idx];
        lse_add(a.x + v.x, m, s);
        lse_add(a.y + v.y, m, s);
        lse_add(a.z + v.z, m, s);
        lse_add(a.w + v.w, m, s);
    }
#pragma unroll
    for (int o = 16; o; o >>= 1) {
        float m2 = __shfl_down_sync(0xffffffffu, m, o);
        float s2 = __shfl_down_sync(0xffffffffu, s, o);
        lse_merge(m2, s2, m, s);
    }
    __shared__ float wm[8], ws[8];
    if ((threadIdx.x & 31) == 0) { wm[threadIdx.x >> 5] = m; ws[threadIdx.x >> 5] = s; }
    __syncthreads();
    if (threadIdx.x == 0) {
#pragma unroll
        for (int w = 1; w < 8; w++) lse_merge(wm[w], ws[w], m, s);
        g_r[b * TT + i] = -(m + logf(s));
    }
}

// ---- final pass: argmax_j(g[i,j] + v_j); scores are exactly 1.0 ----
__global__ void k_argmax(const float* __restrict__ g, float* __restrict__ out) {
    int b = blockIdx.x >> 10;
    int i = blockIdx.x & 1023;
    const float4* gp = (const float4*)(g + ((size_t)(b * TT + i)) * NN);
    const float4* vp = (const float4*)(g_v + b * NN);
    float best = NEG_BIG;
    int bi = 0;
#pragma unroll
    for (int k = 0; k < 8; k++) {
        int idx = threadIdx.x + k * 256;
        float4 a = gp[idx];
        float4 v = vp[idx];
        int j0 = idx * 4;
        float t0 = a.x + v.x, t1 = a.y + v.y, t2 = a.z + v.z, t3 = a.w + v.w;
        if (t0 > best) { best = t0; bi = j0; }
        if (t1 > best) { best = t1; bi = j0 + 1; }
        if (t2 > best) { best = t2; bi = j0 + 2; }
        if (t3 > best) { best = t3; bi = j0 + 3; }
    }
#pragma unroll
    for (int o = 16; o; o >>= 1) {
        float b2 = __shfl_down_sync(0xffffffffu, best, o);
        int i2   = __shfl_down_sync(0xffffffffu, bi, o);
        if (b2 > best || (b2 == best && i2 < bi)) { best = b2; bi = i2; }
    }
    __shared__ float wbv[8];
    __shared__ int wbi[8];
    if ((threadIdx.x & 31) == 0) { wbv[threadIdx.x >> 5] = best; wbi[threadIdx.x >> 5] = bi; }
    __syncthreads();
    if (threadIdx.x == 0) {
#pragma unroll
        for (int w = 1; w < 8; w++) {
            if (wbv[w] > best || (wbv[w] == best && wbi[w] < bi)) { best = wbv[w]; bi = wbi[w]; }
        }
        int o0 = b * TT + i;
        out[o0] = 1.0f;                        // s + stopgrad(1-s) == 1.0 exactly; mask all-true
        out[BB * TT + o0] = (float)bi;         // selected index
    }
}

extern "C" void kernel_launch(void* const* d_in, const int* in_sizes, int n_in,
                              void* d_out, int out_size) {
    const float* x  = (const float*)d_in[0];
    const float* rt = (const float*)d_in[1];
    const float* g  = (const float*)d_in[2];
    float* out = (float*)d_out;

    k_scores<<<(BB * NN * 32 + 255) / 256, 256>>>(x, rt);
    for (int it = 0; it < 8; it++) {
        k_col<<<BB * (NN / 64), 256>>>(g);
        if (it < 7) k_row<<<BB * TT, 256>>>(g);
    }
    k_argmax<<<BB * TT, 256>>>(g, out);
}

// round 2
// speedup vs baseline: 1.7018x; 1.7018x over previous
#include <cuda_runtime.h>
#include <cstdint>

// Problem constants (fixed shapes from setup_inputs)
#define BB 4
#define NN 8192
#define DD 1024
#define TT 1024
#define INV_TEMP (1.0f / 0.7f)
#define NEG_BIG (-3.402823466e38f)

// Scratch (device globals: no allocation allowed)
__device__ float g_sdiv[BB * NN];   // scores / 0.7
__device__ float g_r[BB * TT];      // row offsets r_i
__device__ float g_v[BB * NN];      // v_j = s_j/0.7 + c_j

// ---- branchless online logsumexp helpers (1 MUFU per element, no divergence) ----
__device__ __forceinline__ void lse_add(float v, float& m, float& s) {
    float d = v - m;
    float e = __expf(-fabsf(d));
    bool gt = d > 0.0f;
    s = gt ? __fmaf_rn(s, e, 1.0f) : (s + e);
    m = gt ? v : m;
}
__device__ __forceinline__ void lse_merge(float m2, float s2, float& m, float& s) {
    float d = m2 - m;
    float e = __expf(-fabsf(d));
    bool gt = d > 0.0f;
    s = gt ? __fmaf_rn(s, e, s2) : __fmaf_rn(s2, e, s);
    m = gt ? m2 : m;
}

// ---- kernel 1: scores matvec (b,n,d)x(d) -> sdiv; also zero r ----
__global__ void k_scores(const float* __restrict__ x, const float* __restrict__ rt) {
    int gid = blockIdx.x * blockDim.x + threadIdx.x;
    if (gid < BB * TT) g_r[gid] = 0.0f;
    int gw = gid >> 5;           // one warp per (b, j) row
    int lane = threadIdx.x & 31;
    if (gw >= BB * NN) return;
    const float4* xv = (const float4*)(x + (size_t)gw * DD);
    const float4* rv = (const float4*)rt;
    float acc0 = 0.0f, acc1 = 0.0f;
#pragma unroll
    for (int k = 0; k < 8; k += 2) {
        float4 a0 = xv[lane + 32 * k];
        float4 b0 = __ldg(&rv[lane + 32 * k]);
        float4 a1 = xv[lane + 32 * (k + 1)];
        float4 b1 = __ldg(&rv[lane + 32 * (k + 1)]);
        acc0 += a0.x * b0.x + a0.y * b0.y + a0.z * b0.z + a0.w * b0.w;
        acc1 += a1.x * b1.x + a1.y * b1.y + a1.z * b1.z + a1.w * b1.w;
    }
    float acc = acc0 + acc1;
#pragma unroll
    for (int o = 16; o; o >>= 1) acc += __shfl_down_sync(0xffffffffu, acc, o);
    if (lane == 0) g_sdiv[gw] = acc * INV_TEMP;
}

// ---- col pass: v_j = sdiv_j - lse_i(sdiv_j + g[i,j] + r_i) ----
// block: 512 threads = 64 columns x 8 row-chunks of 128 rows each.
// 2 independent accumulator chains per thread (even/odd local row).
__global__ void __launch_bounds__(512) k_col(const float* __restrict__ g) {
    __shared__ float sr[TT];
    __shared__ float pm[8][64];
    __shared__ float ps[8][64];
    int b    = blockIdx.x >> 7;          // 128 column tiles per batch
    int tile = blockIdx.x & 127;
    int jl    = threadIdx.x & 63;
    int chunk = threadIdx.x >> 6;        // 0..7
    int j = tile * 64 + jl;
    for (int i = threadIdx.x; i < TT; i += 512) sr[i] = g_r[b * TT + i];
    __syncthreads();
    float sd = g_sdiv[b * NN + j];
    const float* gp = g + ((size_t)(b * TT + chunk * 128)) * NN + j;
    const float* rp = sr + chunk * 128;
    float m0 = NEG_BIG, s0 = 0.0f;
    float m1 = NEG_BIG, s1 = 0.0f;
#pragma unroll 4
    for (int i = 0; i < 128; i += 2) {
        float v0 = sd + gp[(size_t)i * NN]       + rp[i];
        float v1 = sd + gp[(size_t)(i + 1) * NN] + rp[i + 1];
        lse_add(v0, m0, s0);
        lse_add(v1, m1, s1);
    }
    lse_merge(m1, s1, m0, s0);
    pm[chunk][jl] = m0; ps[chunk][jl] = s0;
    __syncthreads();
    if (chunk == 0) {
#pragma unroll
        for (int c = 1; c < 8; c++) lse_merge(pm[c][jl], ps[c][jl], m0, s0);
        float lse = m0 + logf(s0);
        g_v[b * NN + j] = sd - lse;
    }
}

// ---- row pass: r_i = -lse_j(g[i,j] + v_j) ----
// one block (256 threads) per (b, i) row; 4 independent chains per thread.
__global__ void __launch_bounds__(256) k_row(const float* __restrict__ g) {
    int b = blockIdx.x >> 10;
    int i = blockIdx.x & 1023;
    const float4* gp = (const float4*)(g + ((size_t)(b * TT + i)) * NN);
    const float4* vp = (const float4*)(g_v + b * NN);
    float mx = NEG_BIG, sx = 0.0f;
    float my = NEG_BIG, sy = 0.0f;
    float mz = NEG_BIG, sz = 0.0f;
    float mw = NEG_BIG, sw = 0.0f;
#pragma unroll
    for (int k = 0; k < 8; k++) {
        int idx = threadIdx.x + k * 256;
        float4 a = gp[idx];
        float4 v = vp[idx];
        lse_add(a.x + v.x, mx, sx);
        lse_add(a.y + v.y, my, sy);
        lse_add(a.z + v.z, mz, sz);
        lse_add(a.w + v.w, mw, sw);
    }
    lse_merge(my, sy, mx, sx);
    lse_merge(mw, sw, mz, sz);
    lse_merge(mz, sz, mx, sx);
#pragma unroll
    for (int o = 16; o; o >>= 1) {
        float m2 = __shfl_down_sync(0xffffffffu, mx, o);
        float s2 = __shfl_down_sync(0xffffffffu, sx, o);
        lse_merge(m2, s2, mx, sx);
    }
    __shared__ float wm[8], ws[8];
    if ((threadIdx.x & 31) == 0) { wm[threadIdx.x >> 5] = mx; ws[threadIdx.x >> 5] = sx; }
    __syncthreads();
    if (threadIdx.x == 0) {
#pragma unroll
        for (int w = 1; w < 8; w++) lse_merge(wm[w], ws[w], mx, sx);
        g_r[b * TT + i] = -(mx + logf(sx));
    }
}

// ---- final pass: argmax_j(g[i,j] + v_j); scores are exactly 1.0 ----
__global__ void __launch_bounds__(256) k_argmax(const float* __restrict__ g, float* __restrict__ out) {
    int b = blockIdx.x >> 10;
    int i = blockIdx.x & 1023;
    const float4* gp = (const float4*)(g + ((size_t)(b * TT + i)) * NN);
    const float4* vp = (const float4*)(g_v + b * NN);
    float b0 = NEG_BIG, b1 = NEG_BIG, b2 = NEG_BIG, b3 = NEG_BIG;
    int i0 = 0, i1 = 0, i2 = 0, i3 = 0;
#pragma unroll
    for (int k = 0; k < 8; k++) {
        int idx = threadIdx.x + k * 256;
        float4 a = gp[idx];
        float4 v = vp[idx];
        int j0 = idx * 4;
        float t0 = a.x + v.x, t1 = a.y + v.y, t2 = a.z + v.z, t3 = a.w + v.w;
        if (t0 > b0) { b0 = t0; i0 = j0; }
        if (t1 > b1) { b1 = t1; i1 = j0 + 1; }
        if (t2 > b2) { b2 = t2; i2 = j0 + 2; }
        if (t3 > b3) { b3 = t3; i3 = j0 + 3; }
    }
    // merge 4 chains; ties resolve to smallest index (argmax semantics)
    if (b1 > b0 || (b1 == b0 && i1 < i0)) { b0 = b1; i0 = i1; }
    if (b3 > b2 || (b3 == b2 && i3 < i2)) { b2 = b3; i2 = i3; }
    if (b2 > b0 || (b2 == b0 && i2 < i0)) { b0 = b2; i0 = i2; }
#pragma unroll
    for (int o = 16; o; o >>= 1) {
        float bv = __shfl_down_sync(0xffffffffu, b0, o);
        int   iv = __shfl_down_sync(0xffffffffu, i0, o);
        if (bv > b0 || (bv == b0 && iv < i0)) { b0 = bv; i0 = iv; }
    }
    __shared__ float wbv[8];
    __shared__ int wbi[8];
    if ((threadIdx.x & 31) == 0) { wbv[threadIdx.x >> 5] = b0; wbi[threadIdx.x >> 5] = i0; }
    __syncthreads();
    if (threadIdx.x == 0) {
#pragma unroll
        for (int w = 1; w < 8; w++) {
            if (wbv[w] > b0 || (wbv[w] == b0 && wbi[w] < i0)) { b0 = wbv[w]; i0 = wbi[w]; }
        }
        int o0 = b * TT + i;
        out[o0] = 1.0f;                        // s + stopgrad(1-s) == 1.0 exactly; mask all-true
        out[BB * TT + o0] = (float)i0;         // selected index
    }
}

extern "C" void kernel_launch(void* const* d_in, const int* in_sizes, int n_in,
                              void* d_out, int out_size) {
    const float* x  = (const float*)d_in[0];
    const float* rt = (const float*)d_in[1];
    const float* g  = (const float*)d_in[2];
    float* out = (float*)d_out;

    k_scores<<<(BB * NN * 32 + 255) / 256, 256>>>(x, rt);
    for (int it = 0; it < 8; it++) {
        k_col<<<BB * (NN / 64), 512>>>(g);
        if (it < 7) k_row<<<BB * TT, 256>>>(g);
    }
    k_argmax<<<BB * TT, 256>>>(g, out);
}

// round 3
// speedup vs baseline: 2.2204x; 1.3047x over previous
#include <cuda_runtime.h>
#include <cstdint>

// Shapes fixed by setup_inputs
#define BB 4
#define NN 8192
#define TT 1024
#define C2 1.4426950408889634f     // log2(e): work entirely in base-2 log domain
#define GB2 66.6f                  // bits; >= 46.1 nats * log2e (gumbel upper bound from clip)
#define NEG_BIG (-3.402823466e38f)

// Scratch (device globals; no allocation allowed)
__device__ float g_r[BB * TT];     // row offsets r'_i (base-2 scaled)
__device__ float g_v[BB * NN];     // col offsets C'_j (base-2 scaled)

__device__ __forceinline__ float ex2(float x) {
    float r; asm("ex2.approx.ftz.f32 %0, %1;" : "=f"(r) : "f"(x)); return r;
}

// Re-init r=0 every call (graph replays must be deterministic)
__global__ void k_init() {
    int i = blockIdx.x * blockDim.x + threadIdx.x;
    if (i < BB * TT) g_r[i] = 0.0f;
}

// ---- col pass over a 2-batch set starting at b0 ----
// C'_j = -( Mc + log2( sum_i 2^( g*C2 + r'_i - Mc ) ) ),  Mc = max_i r' + GB2
// block: 512 thr = 32 cols x 16 chunks x 64 rows. grid: 2 * 256 tiles.
__global__ void __launch_bounds__(512) k_col(const float* __restrict__ g, int b0) {
    __shared__ float rr[TT];        // r' - Mc
    __shared__ float red[17];       // [0..15] warp maxes, [16] broadcast Mc
    __shared__ float ps[16][32];
    int tid = threadIdx.x;
    int jl = tid & 31, chunk = tid >> 5;
    int b = b0 + (blockIdx.x >> 8);
    int tile = blockIdx.x & 255;
    int j = tile * 32 + jl;

    // stage r into shared + block max
    float a0 = g_r[b * TT + tid];
    float a1 = g_r[b * TT + tid + 512];
    float m = fmaxf(a0, a1);
#pragma unroll
    for (int o = 16; o; o >>= 1) m = fmaxf(m, __shfl_xor_sync(~0u, m, o));
    if ((tid & 31) == 0) red[tid >> 5] = m;
    __syncthreads();
    if (tid == 0) {
        float t = red[0];
#pragma unroll
        for (int w = 1; w < 16; w++) t = fmaxf(t, red[w]);
        red[16] = t + GB2;
    }
    __syncthreads();
    float mc = red[16];
    rr[tid] = a0 - mc;
    rr[tid + 512] = a1 - mc;
    __syncthreads();

    const float* gp = g + ((size_t)(b * TT) + (size_t)chunk * 64) * NN + j;
    const float4* rr4 = (const float4*)(rr + chunk * 64);
    float s0 = 0.f, s1 = 0.f, s2 = 0.f, s3 = 0.f;
#pragma unroll 4
    for (int i = 0; i < 16; i++) {
        float4 rv = rr4[i];
        float h0 = gp[(size_t)(4 * i + 0) * NN];
        float h1 = gp[(size_t)(4 * i + 1) * NN];
        float h2 = gp[(size_t)(4 * i + 2) * NN];
        float h3 = gp[(size_t)(4 * i + 3) * NN];
        s0 += ex2(fmaf(h0, C2, rv.x));
        s1 += ex2(fmaf(h1, C2, rv.y));
        s2 += ex2(fmaf(h2, C2, rv.z));
        s3 += ex2(fmaf(h3, C2, rv.w));
    }
    ps[chunk][jl] = (s0 + s1) + (s2 + s3);
    __syncthreads();
    if (chunk == 0) {
        float t = ps[0][jl];
#pragma unroll
        for (int c = 1; c < 16; c++) t += ps[c][jl];
        g_v[b * NN + j] = -(mc + __log2f(t));
    }
}

// ---- row pass over a 2-batch set ----
// r'_i = -( Mr + log2( sum_j 2^( g*C2 + C'_j - Mr ) ) ),  Mr = max_j C' + GB2
// one block (256 thr) per (b,i) row.
__global__ void __launch_bounds__(256) k_row(const float* __restrict__ g, int b0) {
    int b = b0 + (blockIdx.x >> 10);
    int i = blockIdx.x & 1023;
    const float4* gp = (const float4*)(g + ((size_t)(b * TT + i)) * NN);
    const float4* vp = (const float4*)(g_v + (size_t)b * NN);
    int tid = threadIdx.x;
    __shared__ float red[8];
    __shared__ float bc;

    // phase A: cmax over v (32KB, L1/L2-hot)
    float m = NEG_BIG;
#pragma unroll
    for (int k = 0; k < 8; k++) {
        float4 v = vp[tid + k * 256];
        m = fmaxf(m, fmaxf(fmaxf(v.x, v.y), fmaxf(v.z, v.w)));
    }
#pragma unroll
    for (int o = 16; o; o >>= 1) m = fmaxf(m, __shfl_xor_sync(~0u, m, o));
    if ((tid & 31) == 0) red[tid >> 5] = m;
    __syncthreads();
    if (tid == 0) {
        float t = red[0];
#pragma unroll
        for (int w = 1; w < 8; w++) t = fmaxf(t, red[w]);
        bc = t + GB2;
    }
    __syncthreads();
    float M = bc;

    float s0 = 0.f, s1 = 0.f, s2 = 0.f, s3 = 0.f;
#pragma unroll
    for (int k = 0; k < 8; k++) {
        float4 h = gp[tid + k * 256];
        float4 v = vp[tid + k * 256];
        s0 += ex2(fmaf(h.x, C2, v.x - M));
        s1 += ex2(fmaf(h.y, C2, v.y - M));
        s2 += ex2(fmaf(h.z, C2, v.z - M));
        s3 += ex2(fmaf(h.w, C2, v.w - M));
    }
    float s = (s0 + s1) + (s2 + s3);
#pragma unroll
    for (int o = 16; o; o >>= 1) s += __shfl_xor_sync(~0u, s, o);
    __shared__ float rs[8];
    if ((tid & 31) == 0) rs[tid >> 5] = s;
    __syncthreads();
    if (tid == 0) {
        float t = rs[0];
#pragma unroll
        for (int w = 1; w < 8; w++) t += rs[w];
        g_r[b * TT + i] = -(M + __log2f(t));
    }
}

// ---- final: argmax_j( g*C2 + C8'_j ); scores are exactly 1.0 ----
__global__ void __launch_bounds__(256) k_argmax(const float* __restrict__ g,
                                                float* __restrict__ out, int b0) {
    int b = b0 + (blockIdx.x >> 10);
    int i = blockIdx.x & 1023;
    const float4* gp = (const float4*)(g + ((size_t)(b * TT + i)) * NN);
    const float4* vp = (const float4*)(g_v + (size_t)b * NN);
    int tid = threadIdx.x;
    float b0v = NEG_BIG, b1v = NEG_BIG, b2v = NEG_BIG, b3v = NEG_BIG;
    int i0 = 0, i1 = 0, i2 = 0, i3 = 0;
#pragma unroll
    for (int k = 0; k < 8; k++) {
        int idx = tid + k * 256;
        float4 h = gp[idx];
        float4 v = vp[idx];
        int j0 = idx * 4;
        float t0 = fmaf(h.x, C2, v.x), t1 = fmaf(h.y, C2, v.y);
        float t2 = fmaf(h.z, C2, v.z), t3 = fmaf(h.w, C2, v.w);
        if (t0 > b0v) { b0v = t0; i0 = j0; }
        if (t1 > b1v) { b1v = t1; i1 = j0 + 1; }
        if (t2 > b2v) { b2v = t2; i2 = j0 + 2; }
        if (t3 > b3v) { b3v = t3; i3 = j0 + 3; }
    }
    if (b1v > b0v || (b1v == b0v && i1 < i0)) { b0v = b1v; i0 = i1; }
    if (b3v > b2v || (b3v == b2v && i3 < i2)) { b2v = b3v; i2 = i3; }
    if (b2v > b0v || (b2v == b0v && i2 < i0)) { b0v = b2v; i0 = i2; }
#pragma unroll
    for (int o = 16; o; o >>= 1) {
        float bv = __shfl_down_sync(~0u, b0v, o);
        int   iv = __shfl_down_sync(~0u, i0, o);
        if (bv > b0v || (bv == b0v && iv < i0)) { b0v = bv; i0 = iv; }
    }
    __shared__ float wbv[8];
    __shared__ int wbi[8];
    if ((tid & 31) == 0) { wbv[tid >> 5] = b0v; wbi[tid >> 5] = i0; }
    __syncthreads();
    if (tid == 0) {
#pragma unroll
        for (int w = 1; w < 8; w++)
            if (wbv[w] > b0v || (wbv[w] == b0v && wbi[w] < i0)) { b0v = wbv[w]; i0 = wbi[w]; }
        int o0 = b * TT + i;
        out[o0] = 1.0f;                 // s + stopgrad(1-s) == 1.0 exactly; mask all-true
        out[BB * TT + o0] = (float)i0;  // selected index
    }
}

extern "C" void kernel_launch(void* const* d_in, const int* in_sizes, int n_in,
                              void* d_out, int out_size) {
    // d_in[0]=x, d_in[1]=routing_token are mathematically dead (scores cancel in
    // the first axis=-2 normalization). Only gumbel matters.
    const float* g = (const float*)d_in[2];
    float* out = (float*)d_out;

    k_init<<<8, 512>>>();
    // batch-pair sets: keep 64MB gumbel slice L2-resident across all 16 sweeps
    for (int b0 = 0; b0 < BB; b0 += 2) {
        for (int it = 0; it < 8; it++) {
            k_col<<<512, 512>>>(g, b0);
            if (it < 7) k_row<<<2048, 256>>>(g, b0);
        }
        k_argmax<<<2048, 256>>>(g, out, b0);
    }
}